// round 13
// baseline (speedup 1.0000x reference)
#include <cuda_runtime.h>
#include <cuda_fp16.h>
#include <cstdint>
#include <cstddef>

#define B_    2
#define T_    1024
#define MTOK  2048
#define H_    2048
#define V_    32000
#define HK_   16
#define HV_   32
#define DK_   128
#define DV_   128
#define QKDIM 2048
#define VDIM  4096
#define CDIM  8192
#define QW    12416   // combined qkvz+ba output width (12288 qkvz + 64 ba + 64 pad)

typedef __half fp16;

// ==================== scratch ====================
__device__ float g_qkvz[(size_t)MTOK * QW];      // qkvz (cols 0..12287) + ba (12288..12351)
__device__ float g_conv[(size_t)MTOK * CDIM];
__device__ float g_qn[MTOK * QKDIM];
__device__ float g_kn[MTOK * QKDIM];
__device__ float g_g[MTOK * HV_];
__device__ float g_beta[MTOK * HV_];
__device__ float g_o[(size_t)MTOK * VDIM];

__device__ fp16 g_xh[MTOK * H_];
__device__ fp16 g_oh[(size_t)MTOK * VDIM];
__device__ fp16 g_hh[MTOK * H_];
__device__ fp16 g_Wqh[(size_t)QW * H_];          // rows 0..12287 Wqkvz^T, 12288..12351 Wba^T, rest zero-init
__device__ fp16 g_Woh[(size_t)H_ * VDIM];
__device__ fp16 g_Wlh[(size_t)V_ * H_];

// ==================== helpers ====================
__device__ __forceinline__ uint32_t smem_u32(const void* p) {
    uint32_t a;
    asm("{ .reg .u64 t; cvta.to.shared.u64 t, %1; cvt.u32.u64 %0, t; }" : "=r"(a) : "l"(p));
    return a;
}
__device__ __forceinline__ void cpa16(uint32_t dst, const void* src) {
    asm volatile("cp.async.cg.shared.global [%0], [%1], 16;" :: "r"(dst), "l"(src) : "memory");
}
#define CPA_COMMIT() asm volatile("cp.async.commit_group;" ::: "memory")
#define CPA_WAIT2()  asm volatile("cp.async.wait_group 2;" ::: "memory")
#define CPA_WAIT1()  asm volatile("cp.async.wait_group 1;" ::: "memory")

__device__ __forceinline__ void ldm_x4(uint32_t* r, uint32_t addr) {
    asm volatile("ldmatrix.sync.aligned.m8n8.x4.shared.b16 {%0,%1,%2,%3}, [%4];"
                 : "=r"(r[0]), "=r"(r[1]), "=r"(r[2]), "=r"(r[3]) : "r"(addr));
}
__device__ __forceinline__ void mma16816(float* c, const uint32_t* a, const uint32_t* b) {
    asm volatile(
        "mma.sync.aligned.m16n8k16.row.col.f32.f16.f16.f32 "
        "{%0,%1,%2,%3}, {%4,%5,%6,%7}, {%8,%9}, {%0,%1,%2,%3};\n"
        : "+f"(c[0]), "+f"(c[1]), "+f"(c[2]), "+f"(c[3])
        : "r"(a[0]), "r"(a[1]), "r"(a[2]), "r"(a[3]), "r"(b[0]), "r"(b[1]));
}
#define SWZ(off) ((off) ^ (((off) >> 3) & 0x70))

// ==================== fp16 mma.sync GEMM ====================
// CTA tile 256(m) x 128(n), 512 threads = 16 warps (4m x 4n), warp tile 64x32.
// BK=64, 3-stage cp.async pipeline, ldmatrix on SW128-swizzled smem.
#define STG_BYTES 49152     // A: 256*128B = 32KB, B: 128*128B = 16KB
#define O_BH 32768
#define GEMM_SMEM (3 * STG_BYTES + 1024)

__global__ __launch_bounds__(512, 1) void gemm_mma(
    int M, int N, int K,
    const fp16* __restrict__ Ah,
    const fp16* __restrict__ Bh,
    float* __restrict__ Cf, fp16* __restrict__ Chi) {
    extern __shared__ char dsm_raw[];
    uint32_t dbase = (smem_u32(dsm_raw) + 1023u) & ~1023u;

    int tid = threadIdx.x;
    int lane = tid & 31, wid = tid >> 5;
    int wm = wid >> 2, wn = wid & 3;                 // warp tile 64(m) x 32(n)
    int row0 = blockIdx.x << 8;                      // m fastest: weight-stripe L2 reuse
    int col0 = blockIdx.y << 7;

    int lrow = ((lane >> 3) & 1) * 8 + (lane & 7);
    int lbyte = (lane >> 4) * 16;
    int rowA = wm * 64 + lrow;                       // 0..255
    int rowB = wn * 32 + lrow;                       // 0..127

    float acc[4][4][4];
#pragma unroll
    for (int i = 0; i < 4; i++)
#pragma unroll
        for (int j = 0; j < 4; j++)
#pragma unroll
            for (int r = 0; r < 4; r++) acc[i][j][r] = 0.f;

    int nk = K >> 6;

    auto load_stage = [&](int slot, int kc) {
        uint32_t stg = dbase + slot * STG_BYTES;
        int k0 = kc << 6;
        // A: 256 rows x 128B = 2048 chunks of 16B, 4 per thread
#pragma unroll
        for (int i = 0; i < 4; i++) {
            int c = tid + (i << 9);
            int row = c >> 3, c8 = c & 7;
            uint32_t sw = SWZ((uint32_t)(row * 128 + c8 * 16));
            cpa16(stg + sw, Ah + (size_t)(row0 + row) * K + k0 + c8 * 8);
        }
        // B: 128 rows x 128B = 1024 chunks, 2 per thread
#pragma unroll
        for (int i = 0; i < 2; i++) {
            int c = tid + (i << 9);
            int row = c >> 3, c8 = c & 7;
            uint32_t sw = SWZ((uint32_t)(row * 128 + c8 * 16));
            cpa16(stg + O_BH + sw, Bh + (size_t)(col0 + row) * K + k0 + c8 * 8);
        }
    };

    load_stage(0, 0); CPA_COMMIT();
    load_stage(1, 1); CPA_COMMIT();
    load_stage(2, 2); CPA_COMMIT();

    uint32_t fah[2][4][4], fbh[2][4][2];

    auto loadfrag = [&](int buf, uint32_t stg, int kk) {
#pragma unroll
        for (int mi = 0; mi < 4; mi++) {
            uint32_t off = SWZ((uint32_t)((rowA + mi * 16) * 128 + kk * 32 + lbyte));
            ldm_x4(fah[buf][mi], stg + off);
        }
#pragma unroll
        for (int nj = 0; nj < 2; nj++) {
            uint32_t off = SWZ((uint32_t)((rowB + nj * 16) * 128 + kk * 32 + lbyte));
            uint32_t rh[4];
            ldm_x4(rh, stg + O_BH + off);
            fbh[buf][nj * 2][0] = rh[0];     fbh[buf][nj * 2][1] = rh[2];
            fbh[buf][nj * 2 + 1][0] = rh[1]; fbh[buf][nj * 2 + 1][1] = rh[3];
        }
    };

    for (int kc = 0; kc < nk; kc++) {
        CPA_WAIT2();
        __syncthreads();
        uint32_t stg = dbase + (kc % 3) * STG_BYTES;
        loadfrag(0, stg, 0);
#pragma unroll
        for (int kk = 0; kk < 4; kk++) {
            int cur = kk & 1;
            if (kk < 3) loadfrag(cur ^ 1, stg, kk + 1);
#pragma unroll
            for (int mi = 0; mi < 4; mi++)
#pragma unroll
                for (int ni = 0; ni < 4; ni++)
                    mma16816(acc[mi][ni], fah[cur][mi], fbh[cur][ni]);
        }
        __syncthreads();
        if (kc + 3 < nk) load_stage(kc % 3, kc + 3);
        CPA_COMMIT();
    }

    // epilogue
    int g = lane >> 2, tig = lane & 3;
#pragma unroll
    for (int mi = 0; mi < 4; mi++) {
        int r = row0 + wm * 64 + mi * 16 + g;
#pragma unroll
        for (int ni = 0; ni < 4; ni++) {
            int c = col0 + wn * 32 + ni * 8 + 2 * tig;
            float a0 = acc[mi][ni][0], a1 = acc[mi][ni][1];
            float a2 = acc[mi][ni][2], a3 = acc[mi][ni][3];
            if (Cf) {
                *reinterpret_cast<float2*>(Cf + (size_t)r * N + c) = make_float2(a0, a1);
                *reinterpret_cast<float2*>(Cf + (size_t)(r + 8) * N + c) = make_float2(a2, a3);
            }
            if (Chi) {
                *reinterpret_cast<__half2*>(Chi + (size_t)r * N + c) =
                    __halves2half2(__float2half_rn(a0), __float2half_rn(a1));
                *reinterpret_cast<__half2*>(Chi + (size_t)(r + 8) * N + c) =
                    __halves2half2(__float2half_rn(a2), __float2half_rn(a3));
            }
        }
    }
}

// ==================== embed -> fp16 only ====================
__global__ void embed_split_kernel(const int* __restrict__ ids, const float* __restrict__ tab,
                                   fp16* __restrict__ xh) {
    int m = blockIdx.x;
    int id = ids[m];
    const float4* src = reinterpret_cast<const float4*>(tab + (size_t)id * H_);
    __half2* ph = reinterpret_cast<__half2*>(xh) + (size_t)m * (H_ / 2);
    for (int i = threadIdx.x; i < H_ / 4; i += blockDim.x) {
        float4 v = src[i];
        ph[2 * i + 0] = __halves2half2(__float2half_rn(v.x), __float2half_rn(v.y));
        ph[2 * i + 1] = __halves2half2(__float2half_rn(v.z), __float2half_rn(v.w));
    }
}

// ==================== transpose weights to fp16: W[K,N] -> Th[N,K], half2 writes ====================
__global__ __launch_bounds__(256) void tsplit_kernel(const float* __restrict__ W,
                                                     fp16* __restrict__ Th,
                                                     int K, int N) {
    __shared__ float tile[32][33];
    int kb = blockIdx.x << 5, nb = blockIdx.y << 5;
    int tx = threadIdx.x, ty = threadIdx.y;  // (32, 8)
#pragma unroll
    for (int j = 0; j < 4; j++)
        tile[ty + j * 8][tx] = W[(size_t)(kb + ty + j * 8) * N + nb + tx];
    __syncthreads();
    int tid = ty * 32 + tx;
    int n_loc = tid >> 4;          // 0..15
    int k2 = (tid & 15) * 2;       // 0,2,..,30
#pragma unroll
    for (int j = 0; j < 2; j++) {
        int n = n_loc + j * 16;
        __half2 v = __halves2half2(__float2half_rn(tile[k2][n]),
                                   __float2half_rn(tile[k2 + 1][n]));
        *reinterpret_cast<__half2*>(Th + (size_t)(nb + n) * K + kb + k2) = v;
    }
}

// ==================== conv + silu (float4, 4 channels/thread) ====================
__global__ void conv_silu_kernel(const float* __restrict__ qkvz, const float* __restrict__ cw,
                                 const float* __restrict__ cb, float* __restrict__ out) {
    int idx = blockIdx.x * blockDim.x + threadIdx.x;   // over MTOK*CDIM/4
    int c4 = (idx << 2) & (CDIM - 1);
    int m = idx >> 11;                                 // CDIM/4 = 2048
    int t = m & (T_ - 1);
    const float4* wv = reinterpret_cast<const float4*>(cw + c4 * 4);
    float4 w0 = wv[0], w1 = wv[1], w2 = wv[2], w3 = wv[3];
    float4 s = *reinterpret_cast<const float4*>(cb + c4);
    float wtap[4][4] = {{w0.x, w0.y, w0.z, w0.w}, {w1.x, w1.y, w1.z, w1.w},
                        {w2.x, w2.y, w2.z, w2.w}, {w3.x, w3.y, w3.z, w3.w}};
#pragma unroll
    for (int j = 0; j < 4; j++) {
        int tt = t - 3 + j;
        if (tt >= 0) {
            float4 v = *reinterpret_cast<const float4*>(qkvz + (size_t)(m - 3 + j) * QW + c4);
            s.x += wtap[0][j] * v.x;
            s.y += wtap[1][j] * v.y;
            s.z += wtap[2][j] * v.z;
            s.w += wtap[3][j] * v.w;
        }
    }
    s.x = s.x / (1.f + expf(-s.x));
    s.y = s.y / (1.f + expf(-s.y));
    s.z = s.z / (1.f + expf(-s.z));
    s.w = s.w / (1.f + expf(-s.w));
    *reinterpret_cast<float4*>(out + (size_t)m * CDIM + c4) = s;
}

// ==================== l2norm q/k ====================
__global__ __launch_bounds__(128) void norm_qk_kernel(const float* __restrict__ conv,
                                                      float* __restrict__ qn,
                                                      float* __restrict__ kn) {
    int m = blockIdx.x >> 4;
    int hh = blockIdx.x & 15;
    int i = threadIdx.x;
    const float* qr = conv + (size_t)m * CDIM + hh * DK_;
    const float* kr = conv + (size_t)m * CDIM + QKDIM + hh * DK_;
    float qv = qr[i], kv = kr[i];
    float q2 = qv * qv, k2 = kv * kv;
#pragma unroll
    for (int off = 16; off; off >>= 1) {
        q2 += __shfl_xor_sync(0xffffffffu, q2, off);
        k2 += __shfl_xor_sync(0xffffffffu, k2, off);
    }
    __shared__ float shq[4], shk[4];
    if ((i & 31) == 0) { shq[i >> 5] = q2; shk[i >> 5] = k2; }
    __syncthreads();
    float sq = shq[0] + shq[1] + shq[2] + shq[3];
    float sk = shk[0] + shk[1] + shk[2] + shk[3];
    qn[(size_t)m * QKDIM + hh * DK_ + i] = qv * rsqrtf(sq + 1e-6f) * 0.08838834764831845f;
    kn[(size_t)m * QKDIM + hh * DK_ + i] = kv * rsqrtf(sk + 1e-6f);
}

// ==================== gates (reads b,a from combined GEMM output) ====================
__global__ void gates_kernel(const float* __restrict__ qkvz, const float* __restrict__ A_log,
                             const float* __restrict__ dtb, float* __restrict__ g,
                             float* __restrict__ beta) {
    int m = blockIdx.x;
    int h = threadIdx.x;
    float bv = qkvz[(size_t)m * QW + 12288 + h];
    float av = qkvz[(size_t)m * QW + 12320 + h];
    beta[m * HV_ + h] = 1.f / (1.f + expf(-bv));
    float x = av + dtb[h];
    float sp = (x > 20.f) ? x : log1pf(expf(x));
    g[m * HV_ + h] = -expf(A_log[h]) * sp;
}

// ==================== scan (cp.async prefetch + register-cached k/q) ====================
__global__ __launch_bounds__(256) void scan_kernel(const float* __restrict__ qn,
                                                   const float* __restrict__ kn,
                                                   const float* __restrict__ conv,
                                                   const float* __restrict__ gg,
                                                   const float* __restrict__ bb,
                                                   float* __restrict__ o) {
    int bid = blockIdx.x;
    int split = bid & 1;
    int h = (bid >> 1) & 31;
    int b = bid >> 6;
    int kh = h >> 1;
    int v0 = split * 64;
    int tid = threadIdx.x;
    int vloc = tid >> 2;
    int kseg = tid & 3;
    int k0 = kseg * 32;

    __shared__ float sk[3][128], sq[3][128];

    float S[32];
#pragma unroll
    for (int i = 0; i < 32; i++) S[i] = 0.f;

    const float* qrow = qn + (size_t)(b * T_) * QKDIM + kh * DK_;
    const float* krow = kn + (size_t)(b * T_) * QKDIM + kh * DK_;
    const float* vrow = conv + (size_t)(b * T_) * CDIM + 2 * QKDIM + h * DV_ + v0 + vloc;
    const float* grow = gg + (b * T_) * HV_ + h;
    const float* brow = bb + (b * T_) * HV_ + h;
    float* orow = o + (size_t)(b * T_) * VDIM + h * DV_ + v0 + vloc;

    auto prefetch = [&](int t) {
        if (t < T_) {
            int buf = t % 3;
            if (tid < 32)
                cpa16(smem_u32(&sk[buf][tid * 4]), krow + (size_t)t * QKDIM + tid * 4);
            else if (tid < 64)
                cpa16(smem_u32(&sq[buf][(tid - 32) * 4]), qrow + (size_t)t * QKDIM + (tid - 32) * 4);
        }
        CPA_COMMIT();
    };

    prefetch(0);
    float vt0 = vrow[0], gt0 = grow[0], bt0 = brow[0];
    float vt1 = vrow[CDIM], gt1 = grow[HV_], bt1 = brow[HV_];

    for (int t = 0; t < T_; t++) {
        prefetch(t + 1);
        float vt2 = 0.f, gt2 = 0.f, bt2 = 0.f;
        if (t + 2 < T_) {
            vt2 = vrow[(size_t)(t + 2) * CDIM];
            gt2 = grow[(size_t)(t + 2) * HV_];
            bt2 = brow[(size_t)(t + 2) * HV_];
        }
        CPA_WAIT1();
        __syncthreads();
        int buf = t % 3;
        // register-cache k and q rows (64 independent LDS, latency overlapped)
        float kreg[32], qreg[32];
#pragma unroll
        for (int i = 0; i < 32; i++) kreg[i] = sk[buf][k0 + i];
#pragma unroll
        for (int i = 0; i < 32; i++) qreg[i] = sq[buf][k0 + i];
        float decay = expf(gt0);
        float p0 = 0.f, p1 = 0.f, p2 = 0.f, p3 = 0.f;
#pragma unroll
        for (int i = 0; i < 32; i += 4) {
            float s0 = S[i + 0] * decay; S[i + 0] = s0; p0 += kreg[i + 0] * s0;
            float s1 = S[i + 1] * decay; S[i + 1] = s1; p1 += kreg[i + 1] * s1;
            float s2 = S[i + 2] * decay; S[i + 2] = s2; p2 += kreg[i + 2] * s2;
            float s3 = S[i + 3] * decay; S[i + 3] = s3; p3 += kreg[i + 3] * s3;
        }
        float pkv = (p0 + p1) + (p2 + p3);
        pkv += __shfl_xor_sync(0xffffffffu, pkv, 1);
        pkv += __shfl_xor_sync(0xffffffffu, pkv, 2);
        float delta = (vt0 - pkv) * bt0;
        float q0 = 0.f, q1 = 0.f, q2 = 0.f, q3 = 0.f;
#pragma unroll
        for (int i = 0; i < 32; i += 4) {
            float s0 = S[i + 0] + kreg[i + 0] * delta; S[i + 0] = s0; q0 += qreg[i + 0] * s0;
            float s1 = S[i + 1] + kreg[i + 1] * delta; S[i + 1] = s1; q1 += qreg[i + 1] * s1;
            float s2 = S[i + 2] + kreg[i + 2] * delta; S[i + 2] = s2; q2 += qreg[i + 2] * s2;
            float s3 = S[i + 3] + kreg[i + 3] * delta; S[i + 3] = s3; q3 += qreg[i + 3] * s3;
        }
        float po = (q0 + q1) + (q2 + q3);
        po += __shfl_xor_sync(0xffffffffu, po, 1);
        po += __shfl_xor_sync(0xffffffffu, po, 2);
        if (kseg == 0) orow[(size_t)t * VDIM] = po;
        vt0 = vt1; gt0 = gt1; bt0 = bt1;
        vt1 = vt2; gt1 = gt2; bt1 = bt2;
    }
}

// ==================== gated RMSNorm -> fp16 ====================
__global__ __launch_bounds__(128) void gated_norm_split(const float* __restrict__ o,
                                                        const float* __restrict__ qkvz,
                                                        const float* __restrict__ nw,
                                                        fp16* __restrict__ oh) {
    int m = blockIdx.x >> 5;
    int h = blockIdx.x & 31;
    int i = threadIdx.x;
    size_t oidx = (size_t)m * VDIM + h * DV_ + i;
    float ov = o[oidx];
    float zv = qkvz[(size_t)m * QW + 2 * QKDIM + VDIM + h * DV_ + i];
    float gv = ov * (zv / (1.f + expf(-zv)));
    float s2 = gv * gv;
#pragma unroll
    for (int off = 16; off; off >>= 1) s2 += __shfl_xor_sync(0xffffffffu, s2, off);
    __shared__ float sh[4];
    if ((i & 31) == 0) sh[i >> 5] = s2;
    __syncthreads();
    float mean = (sh[0] + sh[1] + sh[2] + sh[3]) * (1.f / 128.f);
    float val = gv * rsqrtf(mean + 1e-6f) * nw[i];
    oh[oidx] = __float2half_rn(val);
}

// ==================== launch ====================
extern "C" void kernel_launch(void* const* d_in, const int* in_sizes, int n_in,
                              void* d_out, int out_size) {
    const int*   ids   = (const int*)d_in[0];
    const float* tab   = (const float*)d_in[1];
    const float* Wqkvz = (const float*)d_in[2];
    const float* Wba   = (const float*)d_in[3];
    const float* cw    = (const float*)d_in[4];
    const float* cb    = (const float*)d_in[5];
    const float* A_log = (const float*)d_in[6];
    const float* dtb   = (const float*)d_in[7];
    const float* nw    = (const float*)d_in[8];
    const float* Wout  = (const float*)d_in[9];
    const float* Wlm   = (const float*)d_in[10];
    float* out = (float*)d_out;

    cudaFuncSetAttribute(gemm_mma, cudaFuncAttributeMaxDynamicSharedMemorySize, GEMM_SMEM);

    float *qkvz, *conv, *qn, *kn, *gg, *bb, *o;
    cudaGetSymbolAddress((void**)&qkvz, g_qkvz);
    cudaGetSymbolAddress((void**)&conv, g_conv);
    cudaGetSymbolAddress((void**)&qn,   g_qn);
    cudaGetSymbolAddress((void**)&kn,   g_kn);
    cudaGetSymbolAddress((void**)&gg,   g_g);
    cudaGetSymbolAddress((void**)&bb,   g_beta);
    cudaGetSymbolAddress((void**)&o,    g_o);

    fp16 *xh, *oh, *hh, *Wqh, *Woh, *Wlh;
    cudaGetSymbolAddress((void**)&xh, g_xh);
    cudaGetSymbolAddress((void**)&oh, g_oh);
    cudaGetSymbolAddress((void**)&hh, g_hh);
    cudaGetSymbolAddress((void**)&Wqh, g_Wqh);
    cudaGetSymbolAddress((void**)&Woh, g_Woh);
    cudaGetSymbolAddress((void**)&Wlh, g_Wlh);

    // weight transpose to fp16: W[K,N] -> [N,K]
    tsplit_kernel<<<dim3(H_ / 32, 12288 / 32), dim3(32, 8)>>>(Wqkvz, Wqh, H_, 12288);
    // Wba[H,64] -> rows 12288..12351 of Wqh (pad rows 12352..12415 stay zero-init)
    tsplit_kernel<<<dim3(H_ / 32, 64 / 32), dim3(32, 8)>>>(Wba, Wqh + (size_t)12288 * H_, H_, 64);
    tsplit_kernel<<<dim3(VDIM / 32, H_ / 32), dim3(32, 8)>>>(Wout, Woh, VDIM, H_);
    tsplit_kernel<<<dim3(H_ / 32, V_ / 32),   dim3(32, 8)>>>(Wlm,  Wlh, H_, V_);

    embed_split_kernel<<<MTOK, 256>>>(ids, tab, xh);
    gemm_mma<<<dim3(MTOK / 256, QW / 128), 512, GEMM_SMEM>>>(
        MTOK, QW, H_, xh, Wqh, qkvz, (fp16*)0);
    conv_silu_kernel<<<(MTOK * CDIM / 4) / 256, 256>>>(qkvz, cw, cb, conv);
    norm_qk_kernel<<<MTOK * HK_, 128>>>(conv, qn, kn);
    gates_kernel<<<MTOK, 32>>>(qkvz, A_log, dtb, gg, bb);
    scan_kernel<<<B_ * HV_ * 2, 256>>>(qn, kn, conv, gg, bb, o);
    gated_norm_split<<<MTOK * HV_, 128>>>(o, qkvz, nw, oh);
    gemm_mma<<<dim3(MTOK / 256, H_ / 128), 512, GEMM_SMEM>>>(
        MTOK, H_, VDIM, oh, Woh, (float*)0, hh);
    gemm_mma<<<dim3(MTOK / 256, V_ / 128), 512, GEMM_SMEM>>>(
        MTOK, V_, H_, hh, Wlh, out, (fp16*)0);
}

// round 14
// speedup vs baseline: 1.0036x; 1.0036x over previous
#include <cuda_runtime.h>
#include <cuda_fp16.h>
#include <cstdint>
#include <cstddef>

#define B_    2
#define T_    1024
#define MTOK  2048
#define H_    2048
#define V_    32000
#define HK_   16
#define HV_   32
#define DK_   128
#define DV_   128
#define QKDIM 2048
#define VDIM  4096
#define CDIM  8192
#define QW    12416   // combined qkvz+ba output width (12288 qkvz + 64 ba + 64 pad)

typedef __half fp16;

// ==================== scratch ====================
__device__ float g_qkvz[(size_t)MTOK * QW];      // qkvz (cols 0..12287) + ba (12288..12351)
__device__ float g_conv[(size_t)MTOK * CDIM];
__device__ float g_qn[MTOK * QKDIM];
__device__ float g_kn[MTOK * QKDIM];
__device__ float g_g[MTOK * HV_];
__device__ float g_beta[MTOK * HV_];
__device__ float g_o[(size_t)MTOK * VDIM];

__device__ fp16 g_xh[MTOK * H_];
__device__ fp16 g_oh[(size_t)MTOK * VDIM];
__device__ fp16 g_hh[MTOK * H_];
__device__ fp16 g_Wqh[(size_t)QW * H_];          // rows 0..12287 Wqkvz^T, 12288..12351 Wba^T, rest zero-init
__device__ fp16 g_Woh[(size_t)H_ * VDIM];
__device__ fp16 g_Wlh[(size_t)V_ * H_];

// ==================== helpers ====================
__device__ __forceinline__ uint32_t smem_u32(const void* p) {
    uint32_t a;
    asm("{ .reg .u64 t; cvta.to.shared.u64 t, %1; cvt.u32.u64 %0, t; }" : "=r"(a) : "l"(p));
    return a;
}
__device__ __forceinline__ void cpa16(uint32_t dst, const void* src) {
    asm volatile("cp.async.cg.shared.global [%0], [%1], 16;" :: "r"(dst), "l"(src) : "memory");
}
#define CPA_COMMIT() asm volatile("cp.async.commit_group;" ::: "memory")
#define CPA_WAIT2()  asm volatile("cp.async.wait_group 2;" ::: "memory")
#define CPA_WAIT1()  asm volatile("cp.async.wait_group 1;" ::: "memory")

__device__ __forceinline__ void ldm_x4(uint32_t* r, uint32_t addr) {
    asm volatile("ldmatrix.sync.aligned.m8n8.x4.shared.b16 {%0,%1,%2,%3}, [%4];"
                 : "=r"(r[0]), "=r"(r[1]), "=r"(r[2]), "=r"(r[3]) : "r"(addr));
}
__device__ __forceinline__ void mma16816(float* c, const uint32_t* a, const uint32_t* b) {
    asm volatile(
        "mma.sync.aligned.m16n8k16.row.col.f32.f16.f16.f32 "
        "{%0,%1,%2,%3}, {%4,%5,%6,%7}, {%8,%9}, {%0,%1,%2,%3};\n"
        : "+f"(c[0]), "+f"(c[1]), "+f"(c[2]), "+f"(c[3])
        : "r"(a[0]), "r"(a[1]), "r"(a[2]), "r"(a[3]), "r"(b[0]), "r"(b[1]));
}
#define SWZ(off) ((off) ^ (((off) >> 3) & 0x70))

// ==================== fp16 mma.sync GEMM (R12-proven config) ====================
// Block 128x128, BK=64, 3-stage cp.async pipeline, ldmatrix on SW128-swizzled smem,
// fragment double-buffering, 256 threads (8 warps, 2m x 4n).
#define STG_BYTES 49152
#define O_BH 32768
#define GEMM_SMEM (3 * STG_BYTES + 1024)

__global__ __launch_bounds__(256, 1) void gemm_mma(
    int M, int N, int K,
    const fp16* __restrict__ Ah,
    const fp16* __restrict__ Bh,
    float* __restrict__ Cf, fp16* __restrict__ Chi) {
    extern __shared__ char dsm_raw[];
    uint32_t dbase = (smem_u32(dsm_raw) + 1023u) & ~1023u;

    int tid = threadIdx.x;
    int lane = tid & 31, wid = tid >> 5;
    int wm = wid >> 2, wn = wid & 3;                 // warp tile 64(m) x 32(n)
    int row0 = blockIdx.x << 7;                      // m fastest: weight-stripe L2 reuse
    int col0 = blockIdx.y << 7;

    int lrow = ((lane >> 3) & 1) * 8 + (lane & 7);
    int lbyte = (lane >> 4) * 16;
    int rowA = wm * 64 + lrow;
    int rowB = wn * 32 + lrow;

    float acc[4][4][4];
#pragma unroll
    for (int i = 0; i < 4; i++)
#pragma unroll
        for (int j = 0; j < 4; j++)
#pragma unroll
            for (int r = 0; r < 4; r++) acc[i][j][r] = 0.f;

    int nk = K >> 6;

    auto load_stage = [&](int slot, int kc) {
        uint32_t stg = dbase + slot * STG_BYTES;
        int k0 = kc << 6;
#pragma unroll
        for (int i = 0; i < 4; i++) {
            int c = tid + (i << 8);
            int row = c >> 3, c8 = c & 7;
            uint32_t sw = SWZ((uint32_t)(row * 128 + c8 * 16));
            size_t ga = (size_t)(row0 + row) * K + k0 + c8 * 8;
            size_t gb = (size_t)(col0 + row) * K + k0 + c8 * 8;
            cpa16(stg + sw, Ah + ga);
            cpa16(stg + O_BH + sw, Bh + gb);
        }
    };

    load_stage(0, 0); CPA_COMMIT();
    load_stage(1, 1); CPA_COMMIT();
    load_stage(2, 2); CPA_COMMIT();

    uint32_t fah[2][4][4], fbh[2][4][2];

    auto loadfrag = [&](int buf, uint32_t stg, int kk) {
#pragma unroll
        for (int mi = 0; mi < 4; mi++) {
            uint32_t off = SWZ((uint32_t)((rowA + mi * 16) * 128 + kk * 32 + lbyte));
            ldm_x4(fah[buf][mi], stg + off);
        }
#pragma unroll
        for (int nj = 0; nj < 2; nj++) {
            uint32_t off = SWZ((uint32_t)((rowB + nj * 16) * 128 + kk * 32 + lbyte));
            uint32_t rh[4];
            ldm_x4(rh, stg + O_BH + off);
            fbh[buf][nj * 2][0] = rh[0];     fbh[buf][nj * 2][1] = rh[2];
            fbh[buf][nj * 2 + 1][0] = rh[1]; fbh[buf][nj * 2 + 1][1] = rh[3];
        }
    };

    for (int kc = 0; kc < nk; kc++) {
        CPA_WAIT2();
        __syncthreads();
        uint32_t stg = dbase + (kc % 3) * STG_BYTES;
        loadfrag(0, stg, 0);
#pragma unroll
        for (int kk = 0; kk < 4; kk++) {
            int cur = kk & 1;
            if (kk < 3) loadfrag(cur ^ 1, stg, kk + 1);
#pragma unroll
            for (int mi = 0; mi < 4; mi++)
#pragma unroll
                for (int ni = 0; ni < 4; ni++)
                    mma16816(acc[mi][ni], fah[cur][mi], fbh[cur][ni]);
        }
        __syncthreads();
        if (kc + 3 < nk) load_stage(kc % 3, kc + 3);
        CPA_COMMIT();
    }

    // epilogue
    int g = lane >> 2, tig = lane & 3;
#pragma unroll
    for (int mi = 0; mi < 4; mi++) {
        int r = row0 + wm * 64 + mi * 16 + g;
#pragma unroll
        for (int ni = 0; ni < 4; ni++) {
            int c = col0 + wn * 32 + ni * 8 + 2 * tig;
            float a0 = acc[mi][ni][0], a1 = acc[mi][ni][1];
            float a2 = acc[mi][ni][2], a3 = acc[mi][ni][3];
            if (Cf) {
                *reinterpret_cast<float2*>(Cf + (size_t)r * N + c) = make_float2(a0, a1);
                *reinterpret_cast<float2*>(Cf + (size_t)(r + 8) * N + c) = make_float2(a2, a3);
            }
            if (Chi) {
                *reinterpret_cast<__half2*>(Chi + (size_t)r * N + c) =
                    __halves2half2(__float2half_rn(a0), __float2half_rn(a1));
                *reinterpret_cast<__half2*>(Chi + (size_t)(r + 8) * N + c) =
                    __halves2half2(__float2half_rn(a2), __float2half_rn(a3));
            }
        }
    }
}

// ==================== embed -> fp16 only ====================
__global__ void embed_split_kernel(const int* __restrict__ ids, const float* __restrict__ tab,
                                   fp16* __restrict__ xh) {
    int m = blockIdx.x;
    int id = ids[m];
    const float4* src = reinterpret_cast<const float4*>(tab + (size_t)id * H_);
    __half2* ph = reinterpret_cast<__half2*>(xh) + (size_t)m * (H_ / 2);
    for (int i = threadIdx.x; i < H_ / 4; i += blockDim.x) {
        float4 v = src[i];
        ph[2 * i + 0] = __halves2half2(__float2half_rn(v.x), __float2half_rn(v.y));
        ph[2 * i + 1] = __halves2half2(__float2half_rn(v.z), __float2half_rn(v.w));
    }
}

// ==================== transpose weights to fp16: W[K,N] -> Th[N,K] ====================
// 64x64 tiles, 256 threads; each output n-row writes 128 contiguous bytes.
__global__ __launch_bounds__(256) void tsplit_kernel(const float* __restrict__ W,
                                                     fp16* __restrict__ Th,
                                                     int K, int N) {
    __shared__ float tile[64][65];   // tile[n][k]
    int kb = blockIdx.x << 6, nb = blockIdx.y << 6;
    int tx = threadIdx.x & 31;       // n within half
    int ty = threadIdx.x >> 5;       // 0..7
    // load: rows k = ty + j*8 (64 rows), cols nb+tx and nb+tx+32
#pragma unroll
    for (int j = 0; j < 8; j++) {
        int k = ty + j * 8;
        const float* src = W + (size_t)(kb + k) * N + nb;
        tile[tx][k]      = src[tx];
        tile[tx + 32][k] = src[tx + 32];
    }
    __syncthreads();
    // store: thread -> (n = tid>>2, 16 consecutive k starting (tid&3)*16)
    int tid = threadIdx.x;
    int n = tid >> 2;
    int kk = (tid & 3) * 16;
    fp16* dst = Th + (size_t)(nb + n) * K + kb + kk;
#pragma unroll
    for (int j = 0; j < 8; j++) {
        __half2 v = __halves2half2(__float2half_rn(tile[n][kk + 2 * j]),
                                   __float2half_rn(tile[n][kk + 2 * j + 1]));
        *reinterpret_cast<__half2*>(dst + 2 * j) = v;
    }
}

// ==================== conv + silu (float4, 4 channels/thread) ====================
__global__ void conv_silu_kernel(const float* __restrict__ qkvz, const float* __restrict__ cw,
                                 const float* __restrict__ cb, float* __restrict__ out) {
    int idx = blockIdx.x * blockDim.x + threadIdx.x;   // over MTOK*CDIM/4
    int c4 = (idx << 2) & (CDIM - 1);
    int m = idx >> 11;                                 // CDIM/4 = 2048
    int t = m & (T_ - 1);
    const float4* wv = reinterpret_cast<const float4*>(cw + c4 * 4);
    float4 w0 = wv[0], w1 = wv[1], w2 = wv[2], w3 = wv[3];
    float4 s = *reinterpret_cast<const float4*>(cb + c4);
    float wtap[4][4] = {{w0.x, w0.y, w0.z, w0.w}, {w1.x, w1.y, w1.z, w1.w},
                        {w2.x, w2.y, w2.z, w2.w}, {w3.x, w3.y, w3.z, w3.w}};
#pragma unroll
    for (int j = 0; j < 4; j++) {
        int tt = t - 3 + j;
        if (tt >= 0) {
            float4 v = *reinterpret_cast<const float4*>(qkvz + (size_t)(m - 3 + j) * QW + c4);
            s.x += wtap[0][j] * v.x;
            s.y += wtap[1][j] * v.y;
            s.z += wtap[2][j] * v.z;
            s.w += wtap[3][j] * v.w;
        }
    }
    s.x = s.x / (1.f + expf(-s.x));
    s.y = s.y / (1.f + expf(-s.y));
    s.z = s.z / (1.f + expf(-s.z));
    s.w = s.w / (1.f + expf(-s.w));
    *reinterpret_cast<float4*>(out + (size_t)m * CDIM + c4) = s;
}

// ==================== l2norm q/k ====================
__global__ __launch_bounds__(128) void norm_qk_kernel(const float* __restrict__ conv,
                                                      float* __restrict__ qn,
                                                      float* __restrict__ kn) {
    int m = blockIdx.x >> 4;
    int hh = blockIdx.x & 15;
    int i = threadIdx.x;
    const float* qr = conv + (size_t)m * CDIM + hh * DK_;
    const float* kr = conv + (size_t)m * CDIM + QKDIM + hh * DK_;
    float qv = qr[i], kv = kr[i];
    float q2 = qv * qv, k2 = kv * kv;
#pragma unroll
    for (int off = 16; off; off >>= 1) {
        q2 += __shfl_xor_sync(0xffffffffu, q2, off);
        k2 += __shfl_xor_sync(0xffffffffu, k2, off);
    }
    __shared__ float shq[4], shk[4];
    if ((i & 31) == 0) { shq[i >> 5] = q2; shk[i >> 5] = k2; }
    __syncthreads();
    float sq = shq[0] + shq[1] + shq[2] + shq[3];
    float sk = shk[0] + shk[1] + shk[2] + shk[3];
    qn[(size_t)m * QKDIM + hh * DK_ + i] = qv * rsqrtf(sq + 1e-6f) * 0.08838834764831845f;
    kn[(size_t)m * QKDIM + hh * DK_ + i] = kv * rsqrtf(sk + 1e-6f);
}

// ==================== gates (reads b,a from combined GEMM output) ====================
__global__ void gates_kernel(const float* __restrict__ qkvz, const float* __restrict__ A_log,
                             const float* __restrict__ dtb, float* __restrict__ g,
                             float* __restrict__ beta) {
    int m = blockIdx.x;
    int h = threadIdx.x;
    float bv = qkvz[(size_t)m * QW + 12288 + h];
    float av = qkvz[(size_t)m * QW + 12320 + h];
    beta[m * HV_ + h] = 1.f / (1.f + expf(-bv));
    float x = av + dtb[h];
    float sp = (x > 20.f) ? x : log1pf(expf(x));
    g[m * HV_ + h] = -expf(A_log[h]) * sp;
}

// ==================== scan (cp.async prefetch + register-cached k/q) ====================
__global__ __launch_bounds__(256) void scan_kernel(const float* __restrict__ qn,
                                                   const float* __restrict__ kn,
                                                   const float* __restrict__ conv,
                                                   const float* __restrict__ gg,
                                                   const float* __restrict__ bb,
                                                   float* __restrict__ o) {
    int bid = blockIdx.x;
    int split = bid & 1;
    int h = (bid >> 1) & 31;
    int b = bid >> 6;
    int kh = h >> 1;
    int v0 = split * 64;
    int tid = threadIdx.x;
    int vloc = tid >> 2;
    int kseg = tid & 3;
    int k0 = kseg * 32;

    __shared__ float sk[3][128], sq[3][128];

    float S[32];
#pragma unroll
    for (int i = 0; i < 32; i++) S[i] = 0.f;

    const float* qrow = qn + (size_t)(b * T_) * QKDIM + kh * DK_;
    const float* krow = kn + (size_t)(b * T_) * QKDIM + kh * DK_;
    const float* vrow = conv + (size_t)(b * T_) * CDIM + 2 * QKDIM + h * DV_ + v0 + vloc;
    const float* grow = gg + (b * T_) * HV_ + h;
    const float* brow = bb + (b * T_) * HV_ + h;
    float* orow = o + (size_t)(b * T_) * VDIM + h * DV_ + v0 + vloc;

    auto prefetch = [&](int t) {
        if (t < T_) {
            int buf = t % 3;
            if (tid < 32)
                cpa16(smem_u32(&sk[buf][tid * 4]), krow + (size_t)t * QKDIM + tid * 4);
            else if (tid < 64)
                cpa16(smem_u32(&sq[buf][(tid - 32) * 4]), qrow + (size_t)t * QKDIM + (tid - 32) * 4);
        }
        CPA_COMMIT();
    };

    prefetch(0);
    float vt0 = vrow[0], gt0 = grow[0], bt0 = brow[0];
    float vt1 = vrow[CDIM], gt1 = grow[HV_], bt1 = brow[HV_];

    for (int t = 0; t < T_; t++) {
        prefetch(t + 1);
        float vt2 = 0.f, gt2 = 0.f, bt2 = 0.f;
        if (t + 2 < T_) {
            vt2 = vrow[(size_t)(t + 2) * CDIM];
            gt2 = grow[(size_t)(t + 2) * HV_];
            bt2 = brow[(size_t)(t + 2) * HV_];
        }
        CPA_WAIT1();
        __syncthreads();
        int buf = t % 3;
        float kreg[32], qreg[32];
#pragma unroll
        for (int i = 0; i < 32; i++) kreg[i] = sk[buf][k0 + i];
#pragma unroll
        for (int i = 0; i < 32; i++) qreg[i] = sq[buf][k0 + i];
        float decay = expf(gt0);
        float p0 = 0.f, p1 = 0.f, p2 = 0.f, p3 = 0.f;
#pragma unroll
        for (int i = 0; i < 32; i += 4) {
            float s0 = S[i + 0] * decay; S[i + 0] = s0; p0 += kreg[i + 0] * s0;
            float s1 = S[i + 1] * decay; S[i + 1] = s1; p1 += kreg[i + 1] * s1;
            float s2 = S[i + 2] * decay; S[i + 2] = s2; p2 += kreg[i + 2] * s2;
            float s3 = S[i + 3] * decay; S[i + 3] = s3; p3 += kreg[i + 3] * s3;
        }
        float pkv = (p0 + p1) + (p2 + p3);
        pkv += __shfl_xor_sync(0xffffffffu, pkv, 1);
        pkv += __shfl_xor_sync(0xffffffffu, pkv, 2);
        float delta = (vt0 - pkv) * bt0;
        float q0 = 0.f, q1 = 0.f, q2 = 0.f, q3 = 0.f;
#pragma unroll
        for (int i = 0; i < 32; i += 4) {
            float s0 = S[i + 0] + kreg[i + 0] * delta; S[i + 0] = s0; q0 += qreg[i + 0] * s0;
            float s1 = S[i + 1] + kreg[i + 1] * delta; S[i + 1] = s1; q1 += qreg[i + 1] * s1;
            float s2 = S[i + 2] + kreg[i + 2] * delta; S[i + 2] = s2; q2 += qreg[i + 2] * s2;
            float s3 = S[i + 3] + kreg[i + 3] * delta; S[i + 3] = s3; q3 += qreg[i + 3] * s3;
        }
        float po = (q0 + q1) + (q2 + q3);
        po += __shfl_xor_sync(0xffffffffu, po, 1);
        po += __shfl_xor_sync(0xffffffffu, po, 2);
        if (kseg == 0) orow[(size_t)t * VDIM] = po;
        vt0 = vt1; gt0 = gt1; bt0 = bt1;
        vt1 = vt2; gt1 = gt2; bt1 = bt2;
    }
}

// ==================== gated RMSNorm -> fp16 ====================
__global__ __launch_bounds__(128) void gated_norm_split(const float* __restrict__ o,
                                                        const float* __restrict__ qkvz,
                                                        const float* __restrict__ nw,
                                                        fp16* __restrict__ oh) {
    int m = blockIdx.x >> 5;
    int h = blockIdx.x & 31;
    int i = threadIdx.x;
    size_t oidx = (size_t)m * VDIM + h * DV_ + i;
    float ov = o[oidx];
    float zv = qkvz[(size_t)m * QW + 2 * QKDIM + VDIM + h * DV_ + i];
    float gv = ov * (zv / (1.f + expf(-zv)));
    float s2 = gv * gv;
#pragma unroll
    for (int off = 16; off; off >>= 1) s2 += __shfl_xor_sync(0xffffffffu, s2, off);
    __shared__ float sh[4];
    if ((i & 31) == 0) sh[i >> 5] = s2;
    __syncthreads();
    float mean = (sh[0] + sh[1] + sh[2] + sh[3]) * (1.f / 128.f);
    float val = gv * rsqrtf(mean + 1e-6f) * nw[i];
    oh[oidx] = __float2half_rn(val);
}

// ==================== launch ====================
extern "C" void kernel_launch(void* const* d_in, const int* in_sizes, int n_in,
                              void* d_out, int out_size) {
    const int*   ids   = (const int*)d_in[0];
    const float* tab   = (const float*)d_in[1];
    const float* Wqkvz = (const float*)d_in[2];
    const float* Wba   = (const float*)d_in[3];
    const float* cw    = (const float*)d_in[4];
    const float* cb    = (const float*)d_in[5];
    const float* A_log = (const float*)d_in[6];
    const float* dtb   = (const float*)d_in[7];
    const float* nw    = (const float*)d_in[8];
    const float* Wout  = (const float*)d_in[9];
    const float* Wlm   = (const float*)d_in[10];
    float* out = (float*)d_out;

    cudaFuncSetAttribute(gemm_mma, cudaFuncAttributeMaxDynamicSharedMemorySize, GEMM_SMEM);

    float *qkvz, *conv, *qn, *kn, *gg, *bb, *o;
    cudaGetSymbolAddress((void**)&qkvz, g_qkvz);
    cudaGetSymbolAddress((void**)&conv, g_conv);
    cudaGetSymbolAddress((void**)&qn,   g_qn);
    cudaGetSymbolAddress((void**)&kn,   g_kn);
    cudaGetSymbolAddress((void**)&gg,   g_g);
    cudaGetSymbolAddress((void**)&bb,   g_beta);
    cudaGetSymbolAddress((void**)&o,    g_o);

    fp16 *xh, *oh, *hh, *Wqh, *Woh, *Wlh;
    cudaGetSymbolAddress((void**)&xh, g_xh);
    cudaGetSymbolAddress((void**)&oh, g_oh);
    cudaGetSymbolAddress((void**)&hh, g_hh);
    cudaGetSymbolAddress((void**)&Wqh, g_Wqh);
    cudaGetSymbolAddress((void**)&Woh, g_Woh);
    cudaGetSymbolAddress((void**)&Wlh, g_Wlh);

    // weight transpose to fp16: W[K,N] -> [N,K]  (64x64 tiles)
    tsplit_kernel<<<dim3(H_ / 64, 12288 / 64), 256>>>(Wqkvz, Wqh, H_, 12288);
    // Wba[H,64] -> rows 12288..12351 of Wqh (pad rows 12352..12415 stay zero-init)
    tsplit_kernel<<<dim3(H_ / 64, 1), 256>>>(Wba, Wqh + (size_t)12288 * H_, H_, 64);
    tsplit_kernel<<<dim3(VDIM / 64, H_ / 64), 256>>>(Wout, Woh, VDIM, H_);
    tsplit_kernel<<<dim3(H_ / 64, V_ / 64),   256>>>(Wlm,  Wlh, H_, V_);

    embed_split_kernel<<<MTOK, 256>>>(ids, tab, xh);
    gemm_mma<<<dim3(MTOK / 128, QW / 128), 256, GEMM_SMEM>>>(
        MTOK, QW, H_, xh, Wqh, qkvz, (fp16*)0);
    conv_silu_kernel<<<(MTOK * CDIM / 4) / 256, 256>>>(qkvz, cw, cb, conv);
    norm_qk_kernel<<<MTOK * HK_, 128>>>(conv, qn, kn);
    gates_kernel<<<MTOK, 32>>>(qkvz, A_log, dtb, gg, bb);
    scan_kernel<<<B_ * HV_ * 2, 256>>>(qn, kn, conv, gg, bb, o);
    gated_norm_split<<<MTOK * HV_, 128>>>(o, qkvz, nw, oh);
    gemm_mma<<<dim3(MTOK / 128, H_ / 128), 256, GEMM_SMEM>>>(
        MTOK, H_, VDIM, oh, Woh, (float*)0, hh);
    gemm_mma<<<dim3(MTOK / 128, V_ / 128), 256, GEMM_SMEM>>>(
        MTOK, V_, H_, hh, Wlh, out, (fp16*)0);
}

// round 15
// speedup vs baseline: 1.0393x; 1.0356x over previous
#include <cuda_runtime.h>
#include <cuda_fp16.h>
#include <cstdint>
#include <cstddef>

#define B_    2
#define T_    1024
#define MTOK  2048
#define H_    2048
#define V_    32000
#define HK_   16
#define HV_   32
#define DK_   128
#define DV_   128
#define QKDIM 2048
#define VDIM  4096
#define CDIM  8192
#define QW    12416   // combined qkvz+ba output width (12288 qkvz + 64 ba + 64 pad)

typedef __half fp16;

// ==================== scratch ====================
__device__ float g_qkvz[(size_t)MTOK * QW];      // qkvz (cols 0..12287) + ba (12288..12351)
__device__ float g_conv[(size_t)MTOK * CDIM];
__device__ float g_qn[MTOK * QKDIM];
__device__ float g_kn[MTOK * QKDIM];
__device__ float g_g[MTOK * HV_];
__device__ float g_beta[MTOK * HV_];
__device__ float g_o[(size_t)MTOK * VDIM];

__device__ fp16 g_xh[MTOK * H_];
__device__ fp16 g_oh[(size_t)MTOK * VDIM];
__device__ fp16 g_hh[MTOK * H_];
__device__ fp16 g_Wqh[(size_t)QW * H_];          // rows 0..12287 Wqkvz^T, 12288..12351 Wba^T, rest zero-init
__device__ fp16 g_Woh[(size_t)H_ * VDIM];
__device__ fp16 g_Wlh[(size_t)V_ * H_];

// ==================== helpers ====================
__device__ __forceinline__ uint32_t smem_u32(const void* p) {
    uint32_t a;
    asm("{ .reg .u64 t; cvta.to.shared.u64 t, %1; cvt.u32.u64 %0, t; }" : "=r"(a) : "l"(p));
    return a;
}
__device__ __forceinline__ void cpa16(uint32_t dst, const void* src) {
    asm volatile("cp.async.cg.shared.global [%0], [%1], 16;" :: "r"(dst), "l"(src) : "memory");
}
#define CPA_COMMIT() asm volatile("cp.async.commit_group;" ::: "memory")
#define CPA_WAIT3()  asm volatile("cp.async.wait_group 3;" ::: "memory")
#define CPA_WAIT1()  asm volatile("cp.async.wait_group 1;" ::: "memory")

__device__ __forceinline__ void ldm_x4(uint32_t* r, uint32_t addr) {
    asm volatile("ldmatrix.sync.aligned.m8n8.x4.shared.b16 {%0,%1,%2,%3}, [%4];"
                 : "=r"(r[0]), "=r"(r[1]), "=r"(r[2]), "=r"(r[3]) : "r"(addr));
}
__device__ __forceinline__ void mma16816(float* c, const uint32_t* a, const uint32_t* b) {
    asm volatile(
        "mma.sync.aligned.m16n8k16.row.col.f32.f16.f16.f32 "
        "{%0,%1,%2,%3}, {%4,%5,%6,%7}, {%8,%9}, {%0,%1,%2,%3};\n"
        : "+f"(c[0]), "+f"(c[1]), "+f"(c[2]), "+f"(c[3])
        : "r"(a[0]), "r"(a[1]), "r"(a[2]), "r"(a[3]), "r"(b[0]), "r"(b[1]));
}
#define SWZ(off) ((off) ^ (((off) >> 3) & 0x70))

// ==================== fp16 mma.sync GEMM (R12 config, 4-stage pipeline) ====================
// Block 128x128, BK=64, 4-stage cp.async pipeline, ldmatrix on SW128-swizzled smem,
// fragment double-buffering, 256 threads (8 warps, 2m x 4n).
#define STG_BYTES 49152
#define O_BH 32768
#define NSTAGE 4
#define GEMM_SMEM (NSTAGE * STG_BYTES + 1024)

__global__ __launch_bounds__(256, 1) void gemm_mma(
    int M, int N, int K,
    const fp16* __restrict__ Ah,
    const fp16* __restrict__ Bh,
    float* __restrict__ Cf, fp16* __restrict__ Chi) {
    extern __shared__ char dsm_raw[];
    uint32_t dbase = (smem_u32(dsm_raw) + 1023u) & ~1023u;

    int tid = threadIdx.x;
    int lane = tid & 31, wid = tid >> 5;
    int wm = wid >> 2, wn = wid & 3;                 // warp tile 64(m) x 32(n)
    int row0 = blockIdx.x << 7;                      // m fastest: weight-stripe L2 reuse
    int col0 = blockIdx.y << 7;

    int lrow = ((lane >> 3) & 1) * 8 + (lane & 7);
    int lbyte = (lane >> 4) * 16;
    int rowA = wm * 64 + lrow;
    int rowB = wn * 32 + lrow;

    float acc[4][4][4];
#pragma unroll
    for (int i = 0; i < 4; i++)
#pragma unroll
        for (int j = 0; j < 4; j++)
#pragma unroll
            for (int r = 0; r < 4; r++) acc[i][j][r] = 0.f;

    int nk = K >> 6;

    auto load_stage = [&](int slot, int kc) {
        uint32_t stg = dbase + slot * STG_BYTES;
        int k0 = kc << 6;
#pragma unroll
        for (int i = 0; i < 4; i++) {
            int c = tid + (i << 8);
            int row = c >> 3, c8 = c & 7;
            uint32_t sw = SWZ((uint32_t)(row * 128 + c8 * 16));
            size_t ga = (size_t)(row0 + row) * K + k0 + c8 * 8;
            size_t gb = (size_t)(col0 + row) * K + k0 + c8 * 8;
            cpa16(stg + sw, Ah + ga);
            cpa16(stg + O_BH + sw, Bh + gb);
        }
    };

    load_stage(0, 0); CPA_COMMIT();
    load_stage(1, 1); CPA_COMMIT();
    load_stage(2, 2); CPA_COMMIT();
    load_stage(3, 3); CPA_COMMIT();

    uint32_t fah[2][4][4], fbh[2][4][2];

    auto loadfrag = [&](int buf, uint32_t stg, int kk) {
#pragma unroll
        for (int mi = 0; mi < 4; mi++) {
            uint32_t off = SWZ((uint32_t)((rowA + mi * 16) * 128 + kk * 32 + lbyte));
            ldm_x4(fah[buf][mi], stg + off);
        }
#pragma unroll
        for (int nj = 0; nj < 2; nj++) {
            uint32_t off = SWZ((uint32_t)((rowB + nj * 16) * 128 + kk * 32 + lbyte));
            uint32_t rh[4];
            ldm_x4(rh, stg + O_BH + off);
            fbh[buf][nj * 2][0] = rh[0];     fbh[buf][nj * 2][1] = rh[2];
            fbh[buf][nj * 2 + 1][0] = rh[1]; fbh[buf][nj * 2 + 1][1] = rh[3];
        }
    };

    for (int kc = 0; kc < nk; kc++) {
        CPA_WAIT3();
        __syncthreads();
        uint32_t stg = dbase + (kc % NSTAGE) * STG_BYTES;
        loadfrag(0, stg, 0);
#pragma unroll
        for (int kk = 0; kk < 4; kk++) {
            int cur = kk & 1;
            if (kk < 3) loadfrag(cur ^ 1, stg, kk + 1);
#pragma unroll
            for (int mi = 0; mi < 4; mi++)
#pragma unroll
                for (int ni = 0; ni < 4; ni++)
                    mma16816(acc[mi][ni], fah[cur][mi], fbh[cur][ni]);
        }
        __syncthreads();
        if (kc + NSTAGE < nk) load_stage(kc % NSTAGE, kc + NSTAGE);
        CPA_COMMIT();
    }

    // epilogue
    int g = lane >> 2, tig = lane & 3;
#pragma unroll
    for (int mi = 0; mi < 4; mi++) {
        int r = row0 + wm * 64 + mi * 16 + g;
#pragma unroll
        for (int ni = 0; ni < 4; ni++) {
            int c = col0 + wn * 32 + ni * 8 + 2 * tig;
            float a0 = acc[mi][ni][0], a1 = acc[mi][ni][1];
            float a2 = acc[mi][ni][2], a3 = acc[mi][ni][3];
            if (Cf) {
                *reinterpret_cast<float2*>(Cf + (size_t)r * N + c) = make_float2(a0, a1);
                *reinterpret_cast<float2*>(Cf + (size_t)(r + 8) * N + c) = make_float2(a2, a3);
            }
            if (Chi) {
                *reinterpret_cast<__half2*>(Chi + (size_t)r * N + c) =
                    __halves2half2(__float2half_rn(a0), __float2half_rn(a1));
                *reinterpret_cast<__half2*>(Chi + (size_t)(r + 8) * N + c) =
                    __halves2half2(__float2half_rn(a2), __float2half_rn(a3));
            }
        }
    }
}

// ==================== embed -> fp16 only ====================
__global__ void embed_split_kernel(const int* __restrict__ ids, const float* __restrict__ tab,
                                   fp16* __restrict__ xh) {
    int m = blockIdx.x;
    int id = ids[m];
    const float4* src = reinterpret_cast<const float4*>(tab + (size_t)id * H_);
    __half2* ph = reinterpret_cast<__half2*>(xh) + (size_t)m * (H_ / 2);
    for (int i = threadIdx.x; i < H_ / 4; i += blockDim.x) {
        float4 v = src[i];
        ph[2 * i + 0] = __halves2half2(__float2half_rn(v.x), __float2half_rn(v.y));
        ph[2 * i + 1] = __halves2half2(__float2half_rn(v.z), __float2half_rn(v.w));
    }
}

// ==================== transpose weights to fp16: W[K,N] -> Th[N,K] (R12 32x32 version) ====================
__global__ __launch_bounds__(256) void tsplit_kernel(const float* __restrict__ W,
                                                     fp16* __restrict__ Th,
                                                     int K, int N) {
    __shared__ float tile[32][33];
    int kb = blockIdx.x << 5, nb = blockIdx.y << 5;
    int tx = threadIdx.x, ty = threadIdx.y;  // (32, 8)
#pragma unroll
    for (int j = 0; j < 4; j++)
        tile[ty + j * 8][tx] = W[(size_t)(kb + ty + j * 8) * N + nb + tx];
    __syncthreads();
    int tid = ty * 32 + tx;
    int n_loc = tid >> 4;          // 0..15
    int k2 = (tid & 15) * 2;       // 0,2,..,30
#pragma unroll
    for (int j = 0; j < 2; j++) {
        int n = n_loc + j * 16;
        __half2 v = __halves2half2(__float2half_rn(tile[k2][n]),
                                   __float2half_rn(tile[k2 + 1][n]));
        *reinterpret_cast<__half2*>(Th + (size_t)(nb + n) * K + kb + k2) = v;
    }
}

// ==================== conv + silu (float4, 4 channels/thread) ====================
__global__ void conv_silu_kernel(const float* __restrict__ qkvz, const float* __restrict__ cw,
                                 const float* __restrict__ cb, float* __restrict__ out) {
    int idx = blockIdx.x * blockDim.x + threadIdx.x;   // over MTOK*CDIM/4
    int c4 = (idx << 2) & (CDIM - 1);
    int m = idx >> 11;                                 // CDIM/4 = 2048
    int t = m & (T_ - 1);
    const float4* wv = reinterpret_cast<const float4*>(cw + c4 * 4);
    float4 w0 = wv[0], w1 = wv[1], w2 = wv[2], w3 = wv[3];
    float4 s = *reinterpret_cast<const float4*>(cb + c4);
    float wtap[4][4] = {{w0.x, w0.y, w0.z, w0.w}, {w1.x, w1.y, w1.z, w1.w},
                        {w2.x, w2.y, w2.z, w2.w}, {w3.x, w3.y, w3.z, w3.w}};
#pragma unroll
    for (int j = 0; j < 4; j++) {
        int tt = t - 3 + j;
        if (tt >= 0) {
            float4 v = *reinterpret_cast<const float4*>(qkvz + (size_t)(m - 3 + j) * QW + c4);
            s.x += wtap[0][j] * v.x;
            s.y += wtap[1][j] * v.y;
            s.z += wtap[2][j] * v.z;
            s.w += wtap[3][j] * v.w;
        }
    }
    s.x = s.x / (1.f + expf(-s.x));
    s.y = s.y / (1.f + expf(-s.y));
    s.z = s.z / (1.f + expf(-s.z));
    s.w = s.w / (1.f + expf(-s.w));
    *reinterpret_cast<float4*>(out + (size_t)m * CDIM + c4) = s;
}

// ==================== l2norm q/k + gates (fused) ====================
__global__ __launch_bounds__(128) void norm_qk_gates_kernel(const float* __restrict__ conv,
                                                            const float* __restrict__ qkvz,
                                                            const float* __restrict__ A_log,
                                                            const float* __restrict__ dtb,
                                                            float* __restrict__ qn,
                                                            float* __restrict__ kn,
                                                            float* __restrict__ gg,
                                                            float* __restrict__ beta) {
    int m = blockIdx.x >> 4;
    int hh = blockIdx.x & 15;
    int i = threadIdx.x;
    const float* qr = conv + (size_t)m * CDIM + hh * DK_;
    const float* kr = conv + (size_t)m * CDIM + QKDIM + hh * DK_;
    float qv = qr[i], kv = kr[i];
    float q2 = qv * qv, k2 = kv * kv;
#pragma unroll
    for (int off = 16; off; off >>= 1) {
        q2 += __shfl_xor_sync(0xffffffffu, q2, off);
        k2 += __shfl_xor_sync(0xffffffffu, k2, off);
    }
    __shared__ float shq[4], shk[4];
    if ((i & 31) == 0) { shq[i >> 5] = q2; shk[i >> 5] = k2; }
    __syncthreads();
    float sq = shq[0] + shq[1] + shq[2] + shq[3];
    float sk = shk[0] + shk[1] + shk[2] + shk[3];
    qn[(size_t)m * QKDIM + hh * DK_ + i] = qv * rsqrtf(sq + 1e-6f) * 0.08838834764831845f;
    kn[(size_t)m * QKDIM + hh * DK_ + i] = kv * rsqrtf(sk + 1e-6f);
    // gates: one block per m handles the 32 heads
    if (hh == 0 && i < HV_) {
        float bv = qkvz[(size_t)m * QW + 12288 + i];
        float av = qkvz[(size_t)m * QW + 12320 + i];
        beta[m * HV_ + i] = 1.f / (1.f + expf(-bv));
        float x = av + dtb[i];
        float sp = (x > 20.f) ? x : log1pf(expf(x));
        gg[m * HV_ + i] = -expf(A_log[i]) * sp;
    }
}

// ==================== scan (R12: cp.async prefetch + split accumulators) ====================
__global__ __launch_bounds__(256) void scan_kernel(const float* __restrict__ qn,
                                                   const float* __restrict__ kn,
                                                   const float* __restrict__ conv,
                                                   const float* __restrict__ gg,
                                                   const float* __restrict__ bb,
                                                   float* __restrict__ o) {
    int bid = blockIdx.x;
    int split = bid & 1;
    int h = (bid >> 1) & 31;
    int b = bid >> 6;
    int kh = h >> 1;
    int v0 = split * 64;
    int tid = threadIdx.x;
    int vloc = tid >> 2;
    int kseg = tid & 3;
    int k0 = kseg * 32;

    __shared__ float sk[3][128], sq[3][128];

    float S[32];
#pragma unroll
    for (int i = 0; i < 32; i++) S[i] = 0.f;

    const float* qrow = qn + (size_t)(b * T_) * QKDIM + kh * DK_;
    const float* krow = kn + (size_t)(b * T_) * QKDIM + kh * DK_;
    const float* vrow = conv + (size_t)(b * T_) * CDIM + 2 * QKDIM + h * DV_ + v0 + vloc;
    const float* grow = gg + (b * T_) * HV_ + h;
    const float* brow = bb + (b * T_) * HV_ + h;
    float* orow = o + (size_t)(b * T_) * VDIM + h * DV_ + v0 + vloc;

    auto prefetch = [&](int t) {
        if (t < T_) {
            int buf = t % 3;
            if (tid < 32)
                cpa16(smem_u32(&sk[buf][tid * 4]), krow + (size_t)t * QKDIM + tid * 4);
            else if (tid < 64)
                cpa16(smem_u32(&sq[buf][(tid - 32) * 4]), qrow + (size_t)t * QKDIM + (tid - 32) * 4);
        }
        CPA_COMMIT();
    };

    prefetch(0);
    float vt0 = vrow[0], gt0 = grow[0], bt0 = brow[0];
    float vt1 = vrow[CDIM], gt1 = grow[HV_], bt1 = brow[HV_];

    for (int t = 0; t < T_; t++) {
        prefetch(t + 1);
        float vt2 = 0.f, gt2 = 0.f, bt2 = 0.f;
        if (t + 2 < T_) {
            vt2 = vrow[(size_t)(t + 2) * CDIM];
            gt2 = grow[(size_t)(t + 2) * HV_];
            bt2 = brow[(size_t)(t + 2) * HV_];
        }
        CPA_WAIT1();
        __syncthreads();
        int buf = t % 3;
        float decay = expf(gt0);
        float p0 = 0.f, p1 = 0.f, p2 = 0.f, p3 = 0.f;
#pragma unroll
        for (int i = 0; i < 32; i += 4) {
            float s0 = S[i + 0] * decay; S[i + 0] = s0; p0 += sk[buf][k0 + i + 0] * s0;
            float s1 = S[i + 1] * decay; S[i + 1] = s1; p1 += sk[buf][k0 + i + 1] * s1;
            float s2 = S[i + 2] * decay; S[i + 2] = s2; p2 += sk[buf][k0 + i + 2] * s2;
            float s3 = S[i + 3] * decay; S[i + 3] = s3; p3 += sk[buf][k0 + i + 3] * s3;
        }
        float pkv = (p0 + p1) + (p2 + p3);
        pkv += __shfl_xor_sync(0xffffffffu, pkv, 1);
        pkv += __shfl_xor_sync(0xffffffffu, pkv, 2);
        float delta = (vt0 - pkv) * bt0;
        float q0 = 0.f, q1 = 0.f, q2 = 0.f, q3 = 0.f;
#pragma unroll
        for (int i = 0; i < 32; i += 4) {
            float s0 = S[i + 0] + sk[buf][k0 + i + 0] * delta; S[i + 0] = s0; q0 += sq[buf][k0 + i + 0] * s0;
            float s1 = S[i + 1] + sk[buf][k0 + i + 1] * delta; S[i + 1] = s1; q1 += sq[buf][k0 + i + 1] * s1;
            float s2 = S[i + 2] + sk[buf][k0 + i + 2] * delta; S[i + 2] = s2; q2 += sq[buf][k0 + i + 2] * s2;
            float s3 = S[i + 3] + sk[buf][k0 + i + 3] * delta; S[i + 3] = s3; q3 += sq[buf][k0 + i + 3] * s3;
        }
        float po = (q0 + q1) + (q2 + q3);
        po += __shfl_xor_sync(0xffffffffu, po, 1);
        po += __shfl_xor_sync(0xffffffffu, po, 2);
        if (kseg == 0) orow[(size_t)t * VDIM] = po;
        vt0 = vt1; gt0 = gt1; bt0 = bt1;
        vt1 = vt2; gt1 = gt2; bt1 = bt2;
    }
}

// ==================== gated RMSNorm -> fp16 ====================
__global__ __launch_bounds__(128) void gated_norm_split(const float* __restrict__ o,
                                                        const float* __restrict__ qkvz,
                                                        const float* __restrict__ nw,
                                                        fp16* __restrict__ oh) {
    int m = blockIdx.x >> 5;
    int h = blockIdx.x & 31;
    int i = threadIdx.x;
    size_t oidx = (size_t)m * VDIM + h * DV_ + i;
    float ov = o[oidx];
    float zv = qkvz[(size_t)m * QW + 2 * QKDIM + VDIM + h * DV_ + i];
    float gv = ov * (zv / (1.f + expf(-zv)));
    float s2 = gv * gv;
#pragma unroll
    for (int off = 16; off; off >>= 1) s2 += __shfl_xor_sync(0xffffffffu, s2, off);
    __shared__ float sh[4];
    if ((i & 31) == 0) sh[i >> 5] = s2;
    __syncthreads();
    float mean = (sh[0] + sh[1] + sh[2] + sh[3]) * (1.f / 128.f);
    float val = gv * rsqrtf(mean + 1e-6f) * nw[i];
    oh[oidx] = __float2half_rn(val);
}

// ==================== launch ====================
extern "C" void kernel_launch(void* const* d_in, const int* in_sizes, int n_in,
                              void* d_out, int out_size) {
    const int*   ids   = (const int*)d_in[0];
    const float* tab   = (const float*)d_in[1];
    const float* Wqkvz = (const float*)d_in[2];
    const float* Wba   = (const float*)d_in[3];
    const float* cw    = (const float*)d_in[4];
    const float* cb    = (const float*)d_in[5];
    const float* A_log = (const float*)d_in[6];
    const float* dtb   = (const float*)d_in[7];
    const float* nw    = (const float*)d_in[8];
    const float* Wout  = (const float*)d_in[9];
    const float* Wlm   = (const float*)d_in[10];
    float* out = (float*)d_out;

    cudaFuncSetAttribute(gemm_mma, cudaFuncAttributeMaxDynamicSharedMemorySize, GEMM_SMEM);

    float *qkvz, *conv, *qn, *kn, *gg, *bb, *o;
    cudaGetSymbolAddress((void**)&qkvz, g_qkvz);
    cudaGetSymbolAddress((void**)&conv, g_conv);
    cudaGetSymbolAddress((void**)&qn,   g_qn);
    cudaGetSymbolAddress((void**)&kn,   g_kn);
    cudaGetSymbolAddress((void**)&gg,   g_g);
    cudaGetSymbolAddress((void**)&bb,   g_beta);
    cudaGetSymbolAddress((void**)&o,    g_o);

    fp16 *xh, *oh, *hh, *Wqh, *Woh, *Wlh;
    cudaGetSymbolAddress((void**)&xh, g_xh);
    cudaGetSymbolAddress((void**)&oh, g_oh);
    cudaGetSymbolAddress((void**)&hh, g_hh);
    cudaGetSymbolAddress((void**)&Wqh, g_Wqh);
    cudaGetSymbolAddress((void**)&Woh, g_Woh);
    cudaGetSymbolAddress((void**)&Wlh, g_Wlh);

    // weight transpose to fp16: W[K,N] -> [N,K]
    tsplit_kernel<<<dim3(H_ / 32, 12288 / 32), dim3(32, 8)>>>(Wqkvz, Wqh, H_, 12288);
    // Wba[H,64] -> rows 12288..12351 of Wqh (pad rows 12352..12415 stay zero-init)
    tsplit_kernel<<<dim3(H_ / 32, 64 / 32), dim3(32, 8)>>>(Wba, Wqh + (size_t)12288 * H_, H_, 64);
    tsplit_kernel<<<dim3(VDIM / 32, H_ / 32), dim3(32, 8)>>>(Wout, Woh, VDIM, H_);
    tsplit_kernel<<<dim3(H_ / 32, V_ / 32),   dim3(32, 8)>>>(Wlm,  Wlh, H_, V_);

    embed_split_kernel<<<MTOK, 256>>>(ids, tab, xh);
    gemm_mma<<<dim3(MTOK / 128, QW / 128), 256, GEMM_SMEM>>>(
        MTOK, QW, H_, xh, Wqh, qkvz, (fp16*)0);
    conv_silu_kernel<<<(MTOK * CDIM / 4) / 256, 256>>>(qkvz, cw, cb, conv);
    norm_qk_gates_kernel<<<MTOK * HK_, 128>>>(conv, qkvz, A_log, dtb, qn, kn, gg, bb);
    scan_kernel<<<B_ * HV_ * 2, 256>>>(qn, kn, conv, gg, bb, o);
    gated_norm_split<<<MTOK * HV_, 128>>>(o, qkvz, nw, oh);
    gemm_mma<<<dim3(MTOK / 128, H_ / 128), 256, GEMM_SMEM>>>(
        MTOK, H_, VDIM, oh, Woh, (float*)0, hh);
    gemm_mma<<<dim3(MTOK / 128, V_ / 128), 256, GEMM_SMEM>>>(
        MTOK, V_, H_, hh, Wlh, out, (fp16*)0);
}